// round 1
// baseline (speedup 1.0000x reference)
#include <cuda_runtime.h>
#include <cstdint>

#define B_ROWS 4096
#define D_IN   2048
#define D_K    4096   // 2 * D_IN (concat)
#define D_HID  16384
#define TOPK   64

// ---- scratch (static __device__ arrays: allocation-free contract) ----
__device__ float g_pre[(size_t)B_ROWS * D_HID];   // 256 MB: encoder pre-activations
__device__ float g_Wtm[(size_t)D_HID * D_IN];     // 128 MB: W_dec_m transposed [h, i]
__device__ float g_Wtp[(size_t)D_HID * D_IN];     // 128 MB: W_dec_p transposed [h, i]
__device__ int   g_idx[B_ROWS * TOPK];
__device__ float g_val[B_ROWS * TOPK];

// ============================================================
// Kernel 1: fp32 encode GEMM.  pre[b,j] = sum_k X[b,k]*W[j,k] + be[j]
// X = concat(x_m, x_p) handled at load time. 128x128 tile, 8x8/thread,
// register-prefetch double buffering.
// ============================================================
__global__ __launch_bounds__(256, 2)
void encode_gemm(const float* __restrict__ xm, const float* __restrict__ xp,
                 const float* __restrict__ W, const float* __restrict__ be)
{
    __shared__ float As[8][128];
    __shared__ float Bs[8][128];

    const int tid = threadIdx.x;
    const int tx = tid & 15;         // N micro
    const int ty = tid >> 4;         // M micro
    const int bx = blockIdx.x;       // N tile (16384/128 = 128)
    const int by = blockIdx.y;       // M tile (4096/128 = 32)

    const int a_m = tid >> 1;
    const int a_k = (tid & 1) * 4;
    const int a_row = by * 128 + a_m;
    const int b_n = tid >> 1;
    const int b_k = (tid & 1) * 4;
    const int b_row = bx * 128 + b_n;

    float acc[8][8];
#pragma unroll
    for (int i = 0; i < 8; i++)
#pragma unroll
        for (int j = 0; j < 8; j++) acc[i][j] = 0.f;

    float4 pa, pb;
    {
        const int gc = a_k;
        const float* srcA = (gc < D_IN) ? (xm + (size_t)a_row * D_IN + gc)
                                        : (xp + (size_t)a_row * D_IN + (gc - D_IN));
        pa = *reinterpret_cast<const float4*>(srcA);
        pb = *reinterpret_cast<const float4*>(W + (size_t)b_row * D_K + b_k);
    }
    As[a_k+0][a_m] = pa.x; As[a_k+1][a_m] = pa.y; As[a_k+2][a_m] = pa.z; As[a_k+3][a_m] = pa.w;
    Bs[b_k+0][b_n] = pb.x; Bs[b_k+1][b_n] = pb.y; Bs[b_k+2][b_n] = pb.z; Bs[b_k+3][b_n] = pb.w;
    __syncthreads();

    for (int kt = 8; kt <= D_K; kt += 8) {
        if (kt < D_K) {
            const int gc = kt + a_k;
            const float* srcA = (gc < D_IN) ? (xm + (size_t)a_row * D_IN + gc)
                                            : (xp + (size_t)a_row * D_IN + (gc - D_IN));
            pa = *reinterpret_cast<const float4*>(srcA);
            pb = *reinterpret_cast<const float4*>(W + (size_t)b_row * D_K + kt + b_k);
        }
#pragma unroll
        for (int k = 0; k < 8; k++) {
            float a[8], bb[8];
            *reinterpret_cast<float4*>(a)    = *reinterpret_cast<const float4*>(&As[k][ty*8]);
            *reinterpret_cast<float4*>(a+4)  = *reinterpret_cast<const float4*>(&As[k][ty*8+4]);
            *reinterpret_cast<float4*>(bb)   = *reinterpret_cast<const float4*>(&Bs[k][tx*8]);
            *reinterpret_cast<float4*>(bb+4) = *reinterpret_cast<const float4*>(&Bs[k][tx*8+4]);
#pragma unroll
            for (int i = 0; i < 8; i++)
#pragma unroll
                for (int j = 0; j < 8; j++)
                    acc[i][j] = fmaf(a[i], bb[j], acc[i][j]);
        }
        __syncthreads();
        if (kt < D_K) {
            As[a_k+0][a_m]=pa.x; As[a_k+1][a_m]=pa.y; As[a_k+2][a_m]=pa.z; As[a_k+3][a_m]=pa.w;
            Bs[b_k+0][b_n]=pb.x; Bs[b_k+1][b_n]=pb.y; Bs[b_k+2][b_n]=pb.z; Bs[b_k+3][b_n]=pb.w;
            __syncthreads();
        }
    }

#pragma unroll
    for (int i = 0; i < 8; i++) {
        const int row = by*128 + ty*8 + i;
        float* dst = g_pre + (size_t)row * D_HID + bx*128 + tx*8;
#pragma unroll
        for (int j0 = 0; j0 < 8; j0 += 4) {
            const int col = bx*128 + tx*8 + j0;
            float4 v;
            v.x = acc[i][j0+0] + be[col+0];
            v.y = acc[i][j0+1] + be[col+1];
            v.z = acc[i][j0+2] + be[col+2];
            v.w = acc[i][j0+3] + be[col+3];
            *reinterpret_cast<float4*>(dst + j0) = v;
        }
    }
}

// ============================================================
// Kernel 2: transpose W_dec_{m,p} [2048, 16384] -> Wt [16384, 2048]
// ============================================================
__global__ __launch_bounds__(256)
void transpose_wdec(const float* __restrict__ Wm, const float* __restrict__ Wp)
{
    const float* src = blockIdx.z ? Wp : Wm;
    float* dst = blockIdx.z ? g_Wtp : g_Wtm;

    __shared__ float tile[32][33];
    const int x = blockIdx.x * 32 + threadIdx.x;   // h (0..16383)
    const int y = blockIdx.y * 32 + threadIdx.y;   // i (0..2047), 8 thread-rows
#pragma unroll
    for (int r = 0; r < 32; r += 8)
        tile[threadIdx.y + r][threadIdx.x] = src[(size_t)(y + r) * D_HID + x];
    __syncthreads();
    const int xo = blockIdx.y * 32 + threadIdx.x;  // i
    const int yo = blockIdx.x * 32 + threadIdx.y;  // h
#pragma unroll
    for (int r = 0; r < 32; r += 8)
        dst[(size_t)(yo + r) * D_IN + xo] = tile[threadIdx.x][threadIdx.y + r];
}

// ============================================================
// Kernel 3: per-row exact top-64 via 4-level radix select on
// order-preserving uint keys; jax-compatible lowest-index tie-break.
// Writes dense z into d_out and compact (idx, val) lists for decode.
// ============================================================
__device__ __forceinline__ unsigned f2key(float f) {
    unsigned u = __float_as_uint(f);
    return (u & 0x80000000u) ? ~u : (u | 0x80000000u);
}

__global__ __launch_bounds__(256)
void topk_kernel(float* __restrict__ out)
{
    const int b = blockIdx.x;
    const float* row = g_pre + (size_t)b * D_HID;
    float* zrow = out + (size_t)2 * B_ROWS * D_IN + (size_t)b * D_HID;
    const int t = threadIdx.x;
    const int lane = t & 31;

    __shared__ unsigned hist[256];
    __shared__ unsigned s_prefix;
    __shared__ int s_kk, s_eqc, s_tiecnt, s_outcnt;
    __shared__ int tielist[256];

    if (t == 0) { s_prefix = 0u; s_kk = TOPK; s_tiecnt = 0; s_outcnt = 0; }

    for (int level = 0; level < 4; level++) {
        const int shift = 24 - 8 * level;
        hist[t] = 0;
        __syncthreads();
        const unsigned prefix = s_prefix;
        const unsigned pmask = (level == 0) ? 0u : (0xFFFFFFFFu << (shift + 8));
        for (int i = t; i < D_HID; i += 256) {
            const unsigned key = f2key(row[i]);
            const bool cand = ((key & pmask) == prefix);
            const unsigned act = __ballot_sync(0xFFFFFFFFu, cand);
            if (cand) {
                const unsigned bucket = (key >> shift) & 0xFFu;
                const unsigned m = __match_any_sync(act, bucket);
                if ((int)(__ffs(m) - 1) == lane)
                    atomicAdd(&hist[bucket], (unsigned)__popc(m));
            }
        }
        __syncthreads();
        if (t == 0) {
            const int kk = s_kk;
            unsigned cum = 0;
            int sel = 0;
            for (int bb2 = 255; bb2 >= 0; --bb2) {
                if (cum + hist[bb2] >= (unsigned)kk) { sel = bb2; break; }
                cum += hist[bb2];
            }
            s_kk = kk - (int)cum;
            s_prefix = prefix | ((unsigned)sel << shift);
            s_eqc = (int)hist[sel];
        }
        __syncthreads();
    }

    const unsigned tau = s_prefix;          // key of the 64th-largest value
    const int tneed = s_kk;                 // how many ==tau to include (>=1)
    const bool tiebreak = (s_eqc != tneed); // need lowest-index selection among ties

    if (tiebreak) {
        for (int i = t; i < D_HID; i += 256) {
            if (f2key(row[i]) == tau) {
                const int p = atomicAdd(&s_tiecnt, 1);
                if (p < 256) tielist[p] = i;
            }
        }
        __syncthreads();
        if (t == 0) {  // insertion-sort the (tiny) tie list ascending by index
            int n = s_tiecnt; if (n > 256) n = 256;
            for (int i = 1; i < n; i++) {
                const int v = tielist[i]; int j = i - 1;
                while (j >= 0 && tielist[j] > v) { tielist[j+1] = tielist[j]; j--; }
                tielist[j+1] = v;
            }
        }
        __syncthreads();
    }

    for (int i = t; i < D_HID; i += 256) {
        const float v = row[i];
        const unsigned key = f2key(v);
        bool take = false;
        if (key > tau) take = true;
        else if (key == tau) {
            if (!tiebreak) take = true;
            else {
                for (int r = 0; r < tneed; r++)
                    if (tielist[r] == i) { take = true; break; }
            }
        }
        zrow[i] = take ? fmaxf(v, 0.f) : 0.f;
        if (take) {
            const int p = atomicAdd(&s_outcnt, 1);
            g_idx[b * TOPK + p] = i;
            g_val[b * TOPK + p] = fmaxf(v, 0.f);
        }
    }
}

// ============================================================
// Kernel 4: sparse fp32 decode. rec[b,i] = sum_j val_j * Wt[idx_j, i]
// One CTA per row b; both decoders; coalesced 8KB row reads of Wt.
// ============================================================
__global__ __launch_bounds__(256)
void decode_kernel(float* __restrict__ out)
{
    const int b = blockIdx.x;
    const int t = threadIdx.x;

    __shared__ int   sidx[TOPK];
    __shared__ float sval[TOPK];
    if (t < TOPK) { sidx[t] = g_idx[b * TOPK + t]; sval[t] = g_val[b * TOPK + t]; }
    __syncthreads();

    float am[8], ap[8];
#pragma unroll
    for (int s = 0; s < 8; s++) { am[s] = 0.f; ap[s] = 0.f; }

#pragma unroll 1
    for (int j = 0; j < TOPK; j++) {
        const int h = sidx[j];
        const float v = sval[j];
        const float* wm = g_Wtm + (size_t)h * D_IN;
        const float* wp = g_Wtp + (size_t)h * D_IN;
#pragma unroll
        for (int s = 0; s < 8; s++) {
            const int c = t + s * 256;
            am[s] = fmaf(v, wm[c], am[s]);
            ap[s] = fmaf(v, wp[c], ap[s]);
        }
    }

    float* om = out + (size_t)b * D_IN;
    float* op = out + (size_t)B_ROWS * D_IN + (size_t)b * D_IN;
#pragma unroll
    for (int s = 0; s < 8; s++) {
        om[t + s * 256] = am[s];
        op[t + s * 256] = ap[s];
    }
}

// ============================================================
extern "C" void kernel_launch(void* const* d_in, const int* in_sizes, int n_in,
                              void* d_out, int out_size)
{
    const float* xm = (const float*)d_in[0];
    const float* xp = (const float*)d_in[1];
    const float* W  = (const float*)d_in[2];
    const float* be = (const float*)d_in[3];
    const float* Wm = (const float*)d_in[4];
    const float* Wp = (const float*)d_in[5];
    // d_in[6] = k (always 64 for this problem; shapes are static)
    float* out = (float*)d_out;

    dim3 g1(D_HID / 128, B_ROWS / 128);
    encode_gemm<<<g1, 256>>>(xm, xp, W, be);

    dim3 g2(D_HID / 32, D_IN / 32, 2);
    transpose_wdec<<<g2, dim3(32, 8)>>>(Wm, Wp);

    topk_kernel<<<B_ROWS, 256>>>(out);

    decode_kernel<<<B_ROWS, 256>>>(out);
}